// round 15
// baseline (speedup 1.0000x reference)
#include <cuda_runtime.h>
#include <cuda_fp16.h>
#include <math.h>
#include <stdint.h>

// ---------------------------------------------------------------------------
// Problem constants
// ---------------------------------------------------------------------------
namespace {
constexpr int Bb   = 2;
constexpr int Hh   = 512;
constexpr int Ww   = 512;
constexpr int Np   = Hh * Ww;
constexpr int Cc   = 48;
constexpr int C3   = 144;
constexpr int HID  = 127;
constexpr int HID2 = 254;
constexpr int NPART  = 512;
constexpr int CHUNK  = Np / NPART;   // 512
constexpr int GSLOTS = 48 * 48 + 96;
}

// ---------------------------------------------------------------------------
// Scratch (fp16 intermediates; fp32 residual-path tensors for precision)
// ---------------------------------------------------------------------------
__device__ float  g_patch[(size_t)Bb * Cc * Np];
__device__ __half g_qkv0 [(size_t)Bb * C3 * Np];
__device__ __half g_qkv  [(size_t)Bb * C3 * Np];
__device__ float  g_first[(size_t)Bb * Cc * Np];
__device__ __half g_hbuf [(size_t)Bb * HID2 * Np];
__device__ __half g_gate [(size_t)Bb * HID * Np];
__device__ float  g_part [(size_t)Bb * NPART * GSLOTS];
__device__ float  g_gfin [Bb * GSLOTS];
__device__ float  g_M    [Bb * 48 * 48];

// ---------------------------------------------------------------------------
// tf32 helpers
// ---------------------------------------------------------------------------
__device__ __forceinline__ uint32_t f2tf(float f) {
  uint32_t r;
  asm("cvt.rna.tf32.f32 %0, %1;" : "=r"(r) : "f"(f));
  return r;
}
__device__ __forceinline__ void mma_tf32(float c[4], uint32_t a0, uint32_t a1,
                                         uint32_t a2, uint32_t a3, uint32_t b0,
                                         uint32_t b1) {
  asm volatile(
      "mma.sync.aligned.m16n8k8.row.col.f32.tf32.tf32.f32 "
      "{%0,%1,%2,%3}, {%4,%5,%6,%7}, {%8,%9}, {%0,%1,%2,%3};"
      : "+f"(c[0]), "+f"(c[1]), "+f"(c[2]), "+f"(c[3])
      : "r"(a0), "r"(a1), "r"(a2), "r"(a3), "r"(b0), "r"(b1));
}

// ---------------------------------------------------------------------------
// K1: patch embed conv 3x3, 3 -> 48 (fp32)
// ---------------------------------------------------------------------------
__global__ __launch_bounds__(128) void k_pe(const float* __restrict__ x,
                                            const float* __restrict__ pw,
                                            float* __restrict__ out) {
  __shared__ float ws[48 * 27];
  __shared__ float si[3][3][514];
  int b = blockIdx.x / Hh, y = blockIdx.x % Hh;
  int tid = threadIdx.x;
  for (int i = tid; i < 48 * 27; i += 128) ws[i] = pw[i];
  for (int i = tid; i < 3 * 3 * 512; i += 128) {
    int ch = i / 1536, r = (i / 512) % 3, xx = i % 512;
    int yy = y - 1 + r;
    float v = (yy >= 0 && yy < Hh)
                  ? x[((size_t)(b * 3 + ch) * Hh + yy) * Ww + xx]
                  : 0.f;
    si[ch][r][xx + 1] = v;
  }
  if (tid < 9) {
    int ch = tid / 3, r = tid % 3;
    si[ch][r][0] = 0.f;
    si[ch][r][513] = 0.f;
  }
  __syncthreads();

  int x0 = tid * 4;
  float rv[3][3][6];
#pragma unroll
  for (int ch = 0; ch < 3; ch++)
#pragma unroll
    for (int r = 0; r < 3; r++)
#pragma unroll
      for (int d = 0; d < 6; d++) rv[ch][r][d] = si[ch][r][x0 + d];

  float* op = out + (size_t)b * Cc * Np + (size_t)y * Ww + x0;
  for (int o = 0; o < 48; o++) {
    float a0 = 0.f, a1 = 0.f, a2 = 0.f, a3 = 0.f;
#pragma unroll
    for (int ch = 0; ch < 3; ch++)
#pragma unroll
      for (int r = 0; r < 3; r++)
#pragma unroll
        for (int dx = 0; dx < 3; dx++) {
          float w = ws[o * 27 + ch * 9 + r * 3 + dx];
          a0 = fmaf(rv[ch][r][dx + 0], w, a0);
          a1 = fmaf(rv[ch][r][dx + 1], w, a1);
          a2 = fmaf(rv[ch][r][dx + 2], w, a2);
          a3 = fmaf(rv[ch][r][dx + 3], w, a3);
        }
    *reinterpret_cast<float4*>(op + (size_t)o * Np) = make_float4(a0, a1, a2, a3);
  }
}

// ---------------------------------------------------------------------------
// Tensor-core pixel GEMM, single-pass tf32, DIRECT-A: weight fragments are
// loaded straight from global (L1/L2-resident broadcast across all pixel
// blocks), eliminating the smem A-tile, its staging loop, and one
// __syncthreads per CO tile.
// ---------------------------------------------------------------------------
template <int K, int KC, int BN, int COT, bool LN, bool RES, bool PBW,
          typename TIN, typename TRES, typename TOUT>
__global__ __launch_bounds__((BN / 16) * 64) void k_tgemm(
    const TIN* __restrict__ in, int in_cs, int in_co,
    const float* __restrict__ w, const float* __restrict__ nw,
    const float* __restrict__ nb, const TRES* __restrict__ res, int res_cs,
    TOUT* __restrict__ out, int out_cs, int CO) {
  static_assert(!LN || K == KC, "LN needs single chunk");
  static_assert(COT == 1 || K == KC, "COT>1 needs single chunk");
  constexpr int MT = BN / 16;
  constexpr int NTH = MT * 64;
  constexpr int SBd = 132;
  constexpr int KSTEPS = KC / 8;

  extern __shared__ uint32_t smu[];
  uint32_t* sB = smu;                 // [KC][SBd]
  float* tail = (float*)(smu + KC * SBd);
  float* mu = tail;
  float* rs = tail + 128;
  float* snw = tail + 256;
  float* snb = tail + 304;
  float* sBf = (float*)sB;

  int tid = threadIdx.x;
  int wid = tid / 32, lane = tid % 32;
  int warp_m = wid % MT, warp_n = wid / MT;
  int n0 = warp_n * 64;
  int pb = blockIdx.y;
  int b = pb / (Np / 128);
  int n0g = (pb % (Np / 128)) * 128;
  int tg = lane & 3, gr = lane >> 2;

  const TIN* ip = in + ((size_t)b * in_cs + in_co) * Np + n0g;
  const float* wp = PBW ? (w + (size_t)b * CO * K) : w;

  float acc[8][4];

  if constexpr (K == KC) {
    // ---- stage B once (vectorized), LN in-place ----
    for (int i = tid; i < KC * 64; i += NTH) {
      int k = i >> 6, j2 = i & 63;
      float2 f;
      if constexpr (sizeof(TIN) == 2)
        f = __half22float2(
            *reinterpret_cast<const __half2*>(ip + (size_t)k * Np + 2 * j2));
      else
        f = *reinterpret_cast<const float2*>(ip + (size_t)k * Np + 2 * j2);
      sBf[k * SBd + 2 * j2] = f.x;
      sBf[k * SBd + 2 * j2 + 1] = f.y;
    }
    if constexpr (LN) {
      for (int i = tid; i < K; i += NTH) {
        snw[i] = nw[i];
        snb[i] = nb[i];
      }
      __syncthreads();
      for (int j = tid; j < 128; j += NTH) {
        float s = 0.f, s2 = 0.f;
#pragma unroll 8
        for (int k = 0; k < K; k++) {
          float xv = sBf[k * SBd + j];
          s += xv;
          s2 = fmaf(xv, xv, s2);
        }
        float m = s * (1.f / (float)K);
        float v = fmaxf(s2 * (1.f / (float)K) - m * m, 0.f);
        mu[j] = m;
        rs[j] = rsqrtf(v + 1e-5f);
      }
      __syncthreads();
      for (int i = tid; i < KC * 128; i += NTH) {
        int k = i >> 7, j = i & 127;
        sB[k * SBd + j] =
            f2tf((sBf[k * SBd + j] - mu[j]) * rs[j] * snw[k] + snb[k]);
      }
    }
    __syncthreads();

#pragma unroll
    for (int ct = 0; ct < COT; ct++) {
      int o0 = ct * BN;
      int om0 = o0 + warp_m * 16 + gr;
      int om1 = om0 + 8;
      bool v0 = (om0 < CO), v1 = (om1 < CO);
      const float* wr0 = wp + (size_t)om0 * K;
      const float* wr1 = wp + (size_t)om1 * K;
#pragma unroll
      for (int j = 0; j < 8; j++)
#pragma unroll
        for (int i = 0; i < 4; i++) acc[j][i] = 0.f;
#pragma unroll
      for (int ks = 0; ks < KSTEPS; ks++) {
        int kr0 = ks * 8 + tg;
        uint32_t ah0 = f2tf(v0 ? wr0[kr0] : 0.f);
        uint32_t ah1 = f2tf(v1 ? wr1[kr0] : 0.f);
        uint32_t ah2 = f2tf(v0 ? wr0[kr0 + 4] : 0.f);
        uint32_t ah3 = f2tf(v1 ? wr1[kr0 + 4] : 0.f);
#pragma unroll
        for (int j = 0; j < 8; j++) {
          uint32_t b0 = sB[kr0 * SBd + n0 + j * 8 + gr];
          uint32_t b1 = sB[(kr0 + 4) * SBd + n0 + j * 8 + gr];
          mma_tf32(acc[j], ah0, ah1, ah2, ah3, b0, b1);
        }
      }
#pragma unroll
      for (int j = 0; j < 8; j++) {
        int nn = n0 + j * 8 + 2 * tg;
#pragma unroll
        for (int h = 0; h < 2; h++) {
          int o = o0 + warp_m * 16 + gr + h * 8;
          if (o < CO) {
            float2 r = make_float2(acc[j][h * 2], acc[j][h * 2 + 1]);
            if constexpr (RES) {
              const TRES* rp = res + ((size_t)b * res_cs + o) * Np + n0g + nn;
              float2 q;
              if constexpr (sizeof(TRES) == 2)
                q = __half22float2(*reinterpret_cast<const __half2*>(rp));
              else
                q = *reinterpret_cast<const float2*>(rp);
              r.x += q.x;
              r.y += q.y;
            }
            if constexpr (sizeof(TOUT) == 2)
              *reinterpret_cast<__half2*>(out + ((size_t)b * out_cs + o) * Np +
                                          n0g + nn) =
                  __floats2half2_rn(r.x, r.y);
            else
              *reinterpret_cast<float2*>(out + ((size_t)b * out_cs + o) * Np +
                                         n0g + nn) = r;
          }
        }
      }
      // no sync needed between CO tiles: sB is read-only here
    }
  } else {
    // ---- chunked-K path (fo: K=127, KC=64) ----
#pragma unroll
    for (int j = 0; j < 8; j++)
#pragma unroll
      for (int i = 0; i < 4; i++) acc[j][i] = 0.f;
    int om0 = warp_m * 16 + gr;
    int om1 = om0 + 8;
    bool v0 = (om0 < CO), v1 = (om1 < CO);
    const float* wr0 = wp + (size_t)om0 * K;
    const float* wr1 = wp + (size_t)om1 * K;
    for (int k0 = 0; k0 < K; k0 += KC) {
      for (int i = tid; i < KC * 64; i += NTH) {
        int k = i >> 6, j2 = i & 63;
        int kk = k0 + k;
        float2 f = make_float2(0.f, 0.f);
        if (kk < K)
          f = __half22float2(
              *reinterpret_cast<const __half2*>(ip + (size_t)kk * Np + 2 * j2));
        sBf[k * SBd + 2 * j2] = f.x;
        sBf[k * SBd + 2 * j2 + 1] = f.y;
      }
      __syncthreads();
#pragma unroll
      for (int ks = 0; ks < KSTEPS; ks++) {
        int kr0 = ks * 8 + tg;
        int kg0 = k0 + kr0, kg1 = k0 + kr0 + 4;
        bool kv0 = (kg0 < K), kv1 = (kg1 < K);
        uint32_t ah0 = f2tf((v0 && kv0) ? wr0[kg0] : 0.f);
        uint32_t ah1 = f2tf((v1 && kv0) ? wr1[kg0] : 0.f);
        uint32_t ah2 = f2tf((v0 && kv1) ? wr0[kg1] : 0.f);
        uint32_t ah3 = f2tf((v1 && kv1) ? wr1[kg1] : 0.f);
#pragma unroll
        for (int j = 0; j < 8; j++) {
          uint32_t b0 = sB[kr0 * SBd + n0 + j * 8 + gr];
          uint32_t b1 = sB[(kr0 + 4) * SBd + n0 + j * 8 + gr];
          mma_tf32(acc[j], ah0, ah1, ah2, ah3, b0, b1);
        }
      }
      if (k0 + KC < K) __syncthreads();
    }
#pragma unroll
    for (int j = 0; j < 8; j++) {
      int nn = n0 + j * 8 + 2 * tg;
#pragma unroll
      for (int h = 0; h < 2; h++) {
        int o = warp_m * 16 + gr + h * 8;
        if (o < CO) {
          float2 r = make_float2(acc[j][h * 2], acc[j][h * 2 + 1]);
          if constexpr (RES) {
            const TRES* rp = res + ((size_t)b * res_cs + o) * Np + n0g + nn;
            float2 q;
            if constexpr (sizeof(TRES) == 2)
              q = __half22float2(*reinterpret_cast<const __half2*>(rp));
            else
              q = *reinterpret_cast<const float2*>(rp);
            r.x += q.x;
            r.y += q.y;
          }
          if constexpr (sizeof(TOUT) == 2)
            *reinterpret_cast<__half2*>(out + ((size_t)b * out_cs + o) * Np +
                                        n0g + nn) = __floats2half2_rn(r.x, r.y);
          else
            *reinterpret_cast<float2*>(out + ((size_t)b * out_cs + o) * Np +
                                       n0g + nn) = r;
        }
      }
    }
  }
}

// ---------------------------------------------------------------------------
// Depthwise 3x3 conv (SAME) on channels [c0, c0+Cn) of a C3-stride buffer,
// fp16 in/out, 16 px per thread (MLP 6).
// ---------------------------------------------------------------------------
__global__ __launch_bounds__(256) void k_dw(const __half* __restrict__ in,
                                            const float* __restrict__ w9,
                                            __half* __restrict__ out, int c0,
                                            int Cn) {
  int idx = blockIdx.x * 256 + threadIdx.x;
  int total = Bb * Cn * Hh * (Ww / 16);
  if (idx >= total) return;
  int xq = idx % (Ww / 16);
  int t = idx / (Ww / 16);
  int y = t % Hh; t /= Hh;
  int c = c0 + (t % Cn);
  int b = t / Cn;
  int x0 = xq * 16;

  float wv[9];
#pragma unroll
  for (int i = 0; i < 9; i++) wv[i] = w9[c * 9 + i];

  const __half* base = in + ((size_t)b * C3 + c) * Np;
  float a[16];
#pragma unroll
  for (int p = 0; p < 16; p++) a[p] = 0.f;

#pragma unroll
  for (int dy = 0; dy < 3; dy++) {
    int yy = y + dy - 1;
    if (yy < 0 || yy >= Hh) continue;
    const __half* row = base + (size_t)yy * Ww;
    float v[18];
    v[0] = (x0 > 0) ? __half2float(row[x0 - 1]) : 0.f;
    uint4 m0 = *reinterpret_cast<const uint4*>(row + x0);
    uint4 m1 = *reinterpret_cast<const uint4*>(row + x0 + 8);
    const __half2* h0 = reinterpret_cast<const __half2*>(&m0);
    const __half2* h1 = reinterpret_cast<const __half2*>(&m1);
#pragma unroll
    for (int q = 0; q < 4; q++) {
      float2 f0 = __half22float2(h0[q]);
      float2 f1 = __half22float2(h1[q]);
      v[1 + 2 * q] = f0.x;
      v[2 + 2 * q] = f0.y;
      v[9 + 2 * q] = f1.x;
      v[10 + 2 * q] = f1.y;
    }
    v[17] = (x0 + 16 < Ww) ? __half2float(row[x0 + 16]) : 0.f;
#pragma unroll
    for (int dx = 0; dx < 3; dx++) {
      float wt = wv[dy * 3 + dx];
#pragma unroll
      for (int p = 0; p < 16; p++) a[p] = fmaf(v[dx + p], wt, a[p]);
    }
  }
  __half2 o8[8];
#pragma unroll
  for (int q = 0; q < 8; q++) o8[q] = __floats2half2_rn(a[2 * q], a[2 * q + 1]);
  __half* op = out + ((size_t)b * C3 + c) * Np + (size_t)y * Ww + x0;
  *reinterpret_cast<uint4*>(op) = *reinterpret_cast<uint4*>(o8);
  *reinterpret_cast<uint4*>(op + 8) = *reinterpret_cast<uint4*>(o8 + 4);
}

// ---------------------------------------------------------------------------
// GDFN: depthwise 3x3 on channels c and c+127, gelu gate; 16 px per thread.
// ---------------------------------------------------------------------------
__global__ __launch_bounds__(128) void k_dwgelu(const __half* __restrict__ in,
                                                const float* __restrict__ w9,
                                                __half* __restrict__ out) {
  int idx = blockIdx.x * 128 + threadIdx.x;
  int total = Bb * HID * Hh * (Ww / 16);
  if (idx >= total) return;
  int xq = idx % (Ww / 16);
  int t = idx / (Ww / 16);
  int y = t % Hh; t /= Hh;
  int c = t % HID;
  int b = t / HID;
  int x0 = xq * 16;

  float w1[9], w2[9];
#pragma unroll
  for (int i = 0; i < 9; i++) {
    w1[i] = w9[c * 9 + i];
    w2[i] = w9[(c + HID) * 9 + i];
  }
  const __half* b1 = in + ((size_t)b * HID2 + c) * Np;
  const __half* b2 = in + ((size_t)b * HID2 + c + HID) * Np;
  float a1[16], a2[16];
#pragma unroll
  for (int p = 0; p < 16; p++) {
    a1[p] = 0.f;
    a2[p] = 0.f;
  }
#pragma unroll
  for (int dy = 0; dy < 3; dy++) {
    int yy = y + dy - 1;
    if (yy < 0 || yy >= Hh) continue;
    const __half* r1 = b1 + (size_t)yy * Ww;
    const __half* r2 = b2 + (size_t)yy * Ww;
    float v1[18], v2[18];
    v1[0] = (x0 > 0) ? __half2float(r1[x0 - 1]) : 0.f;
    v2[0] = (x0 > 0) ? __half2float(r2[x0 - 1]) : 0.f;
    uint4 ma0 = *reinterpret_cast<const uint4*>(r1 + x0);
    uint4 ma1 = *reinterpret_cast<const uint4*>(r1 + x0 + 8);
    uint4 mb0 = *reinterpret_cast<const uint4*>(r2 + x0);
    uint4 mb1 = *reinterpret_cast<const uint4*>(r2 + x0 + 8);
    const __half2* ha0 = reinterpret_cast<const __half2*>(&ma0);
    const __half2* ha1 = reinterpret_cast<const __half2*>(&ma1);
    const __half2* hb0 = reinterpret_cast<const __half2*>(&mb0);
    const __half2* hb1 = reinterpret_cast<const __half2*>(&mb1);
#pragma unroll
    for (int q = 0; q < 4; q++) {
      float2 fa0 = __half22float2(ha0[q]);
      float2 fa1 = __half22float2(ha1[q]);
      float2 fb0 = __half22float2(hb0[q]);
      float2 fb1 = __half22float2(hb1[q]);
      v1[1 + 2 * q] = fa0.x;
      v1[2 + 2 * q] = fa0.y;
      v1[9 + 2 * q] = fa1.x;
      v1[10 + 2 * q] = fa1.y;
      v2[1 + 2 * q] = fb0.x;
      v2[2 + 2 * q] = fb0.y;
      v2[9 + 2 * q] = fb1.x;
      v2[10 + 2 * q] = fb1.y;
    }
    v1[17] = (x0 + 16 < Ww) ? __half2float(r1[x0 + 16]) : 0.f;
    v2[17] = (x0 + 16 < Ww) ? __half2float(r2[x0 + 16]) : 0.f;
#pragma unroll
    for (int dx = 0; dx < 3; dx++) {
      float wa = w1[dy * 3 + dx], wb = w2[dy * 3 + dx];
#pragma unroll
      for (int p = 0; p < 16; p++) {
        a1[p] = fmaf(v1[dx + p], wa, a1[p]);
        a2[p] = fmaf(v2[dx + p], wb, a2[p]);
      }
    }
  }
  __half2 o8[8];
#pragma unroll
  for (int q = 0; q < 8; q++) {
    float u0 = a1[2 * q], u1 = a1[2 * q + 1];
    float g0 = 0.5f * u0 * (1.f + erff(u0 * 0.70710678118654752f)) * a2[2 * q];
    float g1 =
        0.5f * u1 * (1.f + erff(u1 * 0.70710678118654752f)) * a2[2 * q + 1];
    o8[q] = __floats2half2_rn(g0, g1);
  }
  __half* op = out + ((size_t)b * HID + c) * Np + (size_t)y * Ww + x0;
  *reinterpret_cast<uint4*>(op) = *reinterpret_cast<uint4*>(o8);
  *reinterpret_cast<uint4*>(op + 8) = *reinterpret_cast<uint4*>(o8 + 4);
}

// ---------------------------------------------------------------------------
// Gram partials via tensor cores (round-12 proven).
// ---------------------------------------------------------------------------
__global__ __launch_bounds__(192) void k_gram(const __half* __restrict__ qkv,
                                              float* __restrict__ part) {
  constexpr int PS = 36;
  constexpr int BUF = 48 * PS;
  __shared__ uint32_t sQb[2 * BUF];
  __shared__ uint32_t sKb[2 * BUF];
  __shared__ float sN[192];

  int blk = blockIdx.x;
  int b = blk / NPART, pc = blk % NPART;
  int n0 = pc * CHUNK;
  const __half* q = qkv + (size_t)b * C3 * Np;
  const __half* k = q + (size_t)48 * Np;

  int tid = threadIdx.x;
  int wid = tid / 32, lane = tid % 32;
  int tg = lane & 3, gr = lane >> 2;
  int m0 = (wid % 3) * 16;
  int nb = (wid / 3) * 24;

  float acc[3][4];
#pragma unroll
  for (int jt = 0; jt < 3; jt++)
#pragma unroll
    for (int i = 0; i < 4; i++) acc[jt][i] = 0.f;
  float nrm = 0.f;
  int nc = tid % 96, nh = tid / 96;

  auto stage = [&](int sub, int buf) {
    int off = n0 + sub * 32;
    float2* dQ = reinterpret_cast<float2*>(sQb + buf * BUF);
    float2* dK = reinterpret_cast<float2*>(sKb + buf * BUF);
    for (int i = tid; i < 48 * 16; i += 192) {
      int c = i >> 4, j2 = i & 15;
      float2 fq = __half22float2(
          *reinterpret_cast<const __half2*>(q + (size_t)c * Np + off + 2 * j2));
      float2 fk = __half22float2(
          *reinterpret_cast<const __half2*>(k + (size_t)c * Np + off + 2 * j2));
      dQ[c * (PS / 2) + j2] = fq;
      dK[c * (PS / 2) + j2] = fk;
    }
  };

  stage(0, 0);
  __syncthreads();

  constexpr int NSUB = CHUNK / 32;  // 16
  for (int sub = 0; sub < NSUB; sub++) {
    int cur = sub & 1;
    if (sub < NSUB - 1) stage(sub + 1, cur ^ 1);
    uint32_t* sQ = sQb + cur * BUF;
    uint32_t* sK = sKb + cur * BUF;
#pragma unroll
    for (int ks = 0; ks < 4; ks++) {
      int kr0 = ks * 8 + tg;
      uint32_t a0 = sQ[(m0 + gr) * PS + kr0];
      uint32_t a1 = sQ[(m0 + gr + 8) * PS + kr0];
      uint32_t a2 = sQ[(m0 + gr) * PS + kr0 + 4];
      uint32_t a3 = sQ[(m0 + gr + 8) * PS + kr0 + 4];
#pragma unroll
      for (int jt = 0; jt < 3; jt++) {
        uint32_t b0 = sK[(nb + jt * 8 + gr) * PS + kr0];
        uint32_t b1 = sK[(nb + jt * 8 + gr) * PS + kr0 + 4];
        mma_tf32(acc[jt], a0, a1, a2, a3, b0, b1);
      }
    }
    {
      const float2* s2 = (nc < 48)
                             ? (reinterpret_cast<const float2*>(sQ) +
                                nc * (PS / 2))
                             : (reinterpret_cast<const float2*>(sK) +
                                (nc - 48) * (PS / 2));
#pragma unroll
      for (int j2 = nh * 8; j2 < nh * 8 + 8; j2++) {
        float2 v = s2[j2];
        nrm = fmaf(v.x, v.x, fmaf(v.y, v.y, nrm));
      }
    }
    __syncthreads();
  }

  sN[tid] = nrm;
  __syncthreads();
  float* pp = part + (size_t)blk * GSLOTS;
#pragma unroll
  for (int jt = 0; jt < 3; jt++) {
    int col = nb + jt * 8 + 2 * tg;
    pp[(m0 + gr) * 48 + col] = acc[jt][0];
    pp[(m0 + gr) * 48 + col + 1] = acc[jt][1];
    pp[(m0 + gr + 8) * 48 + col] = acc[jt][2];
    pp[(m0 + gr + 8) * 48 + col + 1] = acc[jt][3];
  }
  if (tid < 96) pp[2304 + tid] = sN[tid] + sN[tid + 96];
}

__global__ void k_red(const float* __restrict__ part, float* __restrict__ gfin) {
  int s = blockIdx.x * blockDim.x + threadIdx.x;
  if (s >= Bb * GSLOTS) return;
  int b = s / GSLOTS, slot = s % GSLOTS;
  const float* p = part + (size_t)b * NPART * GSLOTS + slot;
  float a0 = 0.f, a1 = 0.f, a2 = 0.f, a3 = 0.f;
  for (int i = 0; i < NPART; i += 4) {
    a0 += p[(size_t)(i + 0) * GSLOTS];
    a1 += p[(size_t)(i + 1) * GSLOTS];
    a2 += p[(size_t)(i + 2) * GSLOTS];
    a3 += p[(size_t)(i + 3) * GSLOTS];
  }
  gfin[s] = (a0 + a1) + (a2 + a3);
}

__global__ __launch_bounds__(256) void k_att(const float* __restrict__ gfin,
                                             const float* __restrict__ temp,
                                             const float* __restrict__ po,
                                             float* __restrict__ M) {
  __shared__ float sG[2304];
  __shared__ float sAt[2304];
  __shared__ float snq[48], snk[48];
  int b = blockIdx.x, tid = threadIdx.x;
  const float* g = gfin + (size_t)b * GSLOTS;
  for (int i = tid; i < 2304; i += 256) sG[i] = g[i];
  if (tid < 96) {
    float nv = sqrtf(fmaxf(g[2304 + tid], 0.f));
    nv = fmaxf(nv, 1e-12f);
    if (tid < 48) snq[tid] = nv;
    else snk[tid - 48] = nv;
  }
  __syncthreads();
  float tv = temp[0];
  for (int i = tid; i < 2304; i += 256) {
    int c = i / 48, d = i % 48;
    sG[i] = sG[i] * tv / (snq[c] * snk[d]);
  }
  __syncthreads();
  if (tid < 48) {
    float mx = -1e30f;
    for (int d = 0; d < 48; d++) mx = fmaxf(mx, sG[tid * 48 + d]);
    float s = 0.f;
    for (int d = 0; d < 48; d++) {
      float e = expf(sG[tid * 48 + d] - mx);
      sAt[tid * 48 + d] = e;
      s += e;
    }
    float inv = 1.f / s;
    for (int d = 0; d < 48; d++) sAt[tid * 48 + d] *= inv;
  }
  __syncthreads();
  for (int i = tid; i < 2304; i += 256) {
    int o = i / 48, d = i % 48;
    float a = 0.f;
#pragma unroll 8
    for (int c = 0; c < 48; c++) a = fmaf(po[o * 48 + c], sAt[c * 48 + d], a);
    M[(size_t)b * 2304 + i] = a;
  }
}

// ---------------------------------------------------------------------------
// Launch (dw_v forked; direct-A GEMMs)
// ---------------------------------------------------------------------------
extern "C" void kernel_launch(void* const* d_in, const int* in_sizes, int n_in,
                              void* d_out, int out_size) {
  (void)in_sizes; (void)n_in; (void)out_size;
  const float* x      = (const float*)d_in[0];
  const float* pe_w   = (const float*)d_in[1];
  const float* n1_w   = (const float*)d_in[2];
  const float* n1_b   = (const float*)d_in[3];
  const float* temp   = (const float*)d_in[4];
  const float* qkv_w  = (const float*)d_in[5];
  const float* qkv_dw = (const float*)d_in[6];
  const float* po_w   = (const float*)d_in[7];
  const float* n2_w   = (const float*)d_in[8];
  const float* n2_b   = (const float*)d_in[9];
  const float* pi_w   = (const float*)d_in[10];
  const float* ffn_dw = (const float*)d_in[11];
  const float* fo_w   = (const float*)d_in[12];
  float* out = (float*)d_out;

  float *patch, *first, *part, *gfin, *M;
  __half *qkv0, *qkv, *hbuf, *gate;
  cudaGetSymbolAddress((void**)&patch, g_patch);
  cudaGetSymbolAddress((void**)&qkv0,  g_qkv0);
  cudaGetSymbolAddress((void**)&qkv,   g_qkv);
  cudaGetSymbolAddress((void**)&first, g_first);
  cudaGetSymbolAddress((void**)&hbuf,  g_hbuf);
  cudaGetSymbolAddress((void**)&gate,  g_gate);
  cudaGetSymbolAddress((void**)&part,  g_part);
  cudaGetSymbolAddress((void**)&gfin,  g_gfin);
  cudaGetSymbolAddress((void**)&M,     g_M);

  // smem: sB(KC*132 u32) + 352-float tail (A tile eliminated)
  constexpr int SM_48 = (48 * 132 + 352) * 4;   // 26752
  constexpr int SM_64 = (64 * 132 + 352) * 4;   // 35200

  static cudaStream_t s2 = nullptr;
  static cudaEvent_t evFork = nullptr, evJoin = nullptr;
  if (s2 == nullptr) {
    cudaStreamCreateWithFlags(&s2, cudaStreamNonBlocking);
    cudaEventCreateWithFlags(&evFork, cudaEventDisableTiming);
    cudaEventCreateWithFlags(&evJoin, cudaEventDisableTiming);
  }

  int gpix = Bb * Np / 128;  // 4096 pixel-tiles

  // 1. patch embed (fp32)
  k_pe<<<Bb * Hh, 128>>>(x, pe_w, patch);

  // 2. LN(patch) -> qkv 1x1 (48 -> 144), fp16 out; 3 CO-tiles per block
  k_tgemm<48, 48, 48, 3, true, false, false, float, float, __half>
      <<<dim3(1, gpix), 192, SM_48>>>(patch, Cc, 0, qkv_w, n1_w, n1_b,
                                      nullptr, 0, qkv0, C3, C3);

  // fork: dw on v-channels runs concurrently with dw_qk + gram chain
  cudaEventRecord(evFork, 0);
  cudaStreamWaitEvent(s2, evFork, 0);
  k_dw<<<(Bb * 48 * Hh * (Ww / 16) + 255) / 256, 256, 0, s2>>>(
      qkv0, qkv_dw, qkv, 96, 48);
  cudaEventRecord(evJoin, s2);

  // 3. depthwise 3x3 on q,k channels (stream 0)
  k_dw<<<(Bb * 96 * Hh * (Ww / 16) + 255) / 256, 256>>>(qkv0, qkv_dw, qkv, 0,
                                                        96);

  // 4-6. gram -> reduce -> softmax + fold po_w into M
  k_gram<<<Bb * NPART, 192>>>(qkv, part);
  k_red<<<(Bb * GSLOTS + 255) / 256, 256>>>(part, gfin);
  k_att<<<Bb, 256>>>(gfin, temp, po_w, M);

  // join: attn-v GEMM needs dw'd v
  cudaStreamWaitEvent((cudaStream_t)0, evJoin, 0);

  // 7. first = patch + M @ v
  k_tgemm<48, 48, 48, 1, false, true, true, __half, float, float>
      <<<dim3(1, gpix), 192, SM_48>>>(qkv, C3, 96, M, nullptr, nullptr, patch,
                                      Cc, first, Cc, Cc);

  // 8. LN(first) -> pi 1x1 (48 -> 254), fp16 out; 4 CO-tiles per block
  k_tgemm<48, 48, 64, 4, true, false, false, float, float, __half>
      <<<dim3(1, gpix), 256, SM_48>>>(first, Cc, 0, pi_w, n2_w, n2_b, nullptr,
                                      0, hbuf, HID2, HID2);

  // 9. depthwise 3x3 + exact-gelu gating (254 -> 127), fp16, 16 px/thread
  k_dwgelu<<<(Bb * HID * Hh * (Ww / 16) + 127) / 128, 128>>>(hbuf, ffn_dw,
                                                             gate);

  // 10. out = first + fo 1x1 (127 -> 48), fp32 out
  k_tgemm<127, 64, 48, 1, false, true, false, __half, float, float>
      <<<dim3(1, gpix), 192, SM_64>>>(gate, HID, 0, fo_w, nullptr, nullptr,
                                      first, Cc, out, Cc, Cc);
}

// round 16
// speedup vs baseline: 1.3786x; 1.3786x over previous
#include <cuda_runtime.h>
#include <cuda_fp16.h>
#include <math.h>
#include <stdint.h>

// ---------------------------------------------------------------------------
// Problem constants
// ---------------------------------------------------------------------------
namespace {
constexpr int Bb   = 2;
constexpr int Hh   = 512;
constexpr int Ww   = 512;
constexpr int Np   = Hh * Ww;
constexpr int Cc   = 48;
constexpr int C3   = 144;
constexpr int HID  = 127;
constexpr int HID2 = 254;
constexpr int NPART  = 512;
constexpr int CHUNK  = Np / NPART;   // 512
constexpr int GSLOTS = 48 * 48 + 96;
}

// ---------------------------------------------------------------------------
// Scratch (fp16 intermediates; fp32 residual-path tensors for precision)
// ---------------------------------------------------------------------------
__device__ float  g_patch[(size_t)Bb * Cc * Np];
__device__ __half g_qkv0 [(size_t)Bb * C3 * Np];
__device__ __half g_qkv  [(size_t)Bb * C3 * Np];
__device__ float  g_first[(size_t)Bb * Cc * Np];
__device__ __half g_hbuf [(size_t)Bb * HID2 * Np];
__device__ __half g_gate [(size_t)Bb * HID * Np];
__device__ float  g_part [(size_t)Bb * NPART * GSLOTS];
__device__ float  g_gfin [Bb * GSLOTS];
__device__ float  g_M    [Bb * 48 * 48];

// ---------------------------------------------------------------------------
// tf32 helpers
// ---------------------------------------------------------------------------
__device__ __forceinline__ uint32_t f2tf(float f) {
  uint32_t r;
  asm("cvt.rna.tf32.f32 %0, %1;" : "=r"(r) : "f"(f));
  return r;
}
__device__ __forceinline__ void mma_tf32(float c[4], uint32_t a0, uint32_t a1,
                                         uint32_t a2, uint32_t a3, uint32_t b0,
                                         uint32_t b1) {
  asm volatile(
      "mma.sync.aligned.m16n8k8.row.col.f32.tf32.tf32.f32 "
      "{%0,%1,%2,%3}, {%4,%5,%6,%7}, {%8,%9}, {%0,%1,%2,%3};"
      : "+f"(c[0]), "+f"(c[1]), "+f"(c[2]), "+f"(c[3])
      : "r"(a0), "r"(a1), "r"(a2), "r"(a3), "r"(b0), "r"(b1));
}

// ---------------------------------------------------------------------------
// K1: patch embed conv 3x3, 3 -> 48 (fp32)
// ---------------------------------------------------------------------------
__global__ __launch_bounds__(128) void k_pe(const float* __restrict__ x,
                                            const float* __restrict__ pw,
                                            float* __restrict__ out) {
  __shared__ float ws[48 * 27];
  __shared__ float si[3][3][514];
  int b = blockIdx.x / Hh, y = blockIdx.x % Hh;
  int tid = threadIdx.x;
  for (int i = tid; i < 48 * 27; i += 128) ws[i] = pw[i];
  for (int i = tid; i < 3 * 3 * 512; i += 128) {
    int ch = i / 1536, r = (i / 512) % 3, xx = i % 512;
    int yy = y - 1 + r;
    float v = (yy >= 0 && yy < Hh)
                  ? x[((size_t)(b * 3 + ch) * Hh + yy) * Ww + xx]
                  : 0.f;
    si[ch][r][xx + 1] = v;
  }
  if (tid < 9) {
    int ch = tid / 3, r = tid % 3;
    si[ch][r][0] = 0.f;
    si[ch][r][513] = 0.f;
  }
  __syncthreads();

  int x0 = tid * 4;
  float rv[3][3][6];
#pragma unroll
  for (int ch = 0; ch < 3; ch++)
#pragma unroll
    for (int r = 0; r < 3; r++)
#pragma unroll
      for (int d = 0; d < 6; d++) rv[ch][r][d] = si[ch][r][x0 + d];

  float* op = out + (size_t)b * Cc * Np + (size_t)y * Ww + x0;
  for (int o = 0; o < 48; o++) {
    float a0 = 0.f, a1 = 0.f, a2 = 0.f, a3 = 0.f;
#pragma unroll
    for (int ch = 0; ch < 3; ch++)
#pragma unroll
      for (int r = 0; r < 3; r++)
#pragma unroll
        for (int dx = 0; dx < 3; dx++) {
          float w = ws[o * 27 + ch * 9 + r * 3 + dx];
          a0 = fmaf(rv[ch][r][dx + 0], w, a0);
          a1 = fmaf(rv[ch][r][dx + 1], w, a1);
          a2 = fmaf(rv[ch][r][dx + 2], w, a2);
          a3 = fmaf(rv[ch][r][dx + 3], w, a3);
        }
    *reinterpret_cast<float4*>(op + (size_t)o * Np) = make_float4(a0, a1, a2, a3);
  }
}

// ---------------------------------------------------------------------------
// Tensor-core pixel GEMM, single-pass tf32, smem A-tile (round-14 proven),
// with COALESCED A staging (k fastest across threads).
// ---------------------------------------------------------------------------
template <int K, int KC, int BN, int COT, bool LN, bool RES, bool PBW,
          typename TIN, typename TRES, typename TOUT>
__global__ __launch_bounds__((BN / 16) * 64) void k_tgemm(
    const TIN* __restrict__ in, int in_cs, int in_co,
    const float* __restrict__ w, const float* __restrict__ nw,
    const float* __restrict__ nb, const TRES* __restrict__ res, int res_cs,
    TOUT* __restrict__ out, int out_cs, int CO) {
  static_assert(!LN || K == KC, "LN needs single chunk");
  static_assert(COT == 1 || K == KC, "COT>1 needs single chunk");
  constexpr int MT = BN / 16;
  constexpr int NTH = MT * 64;
  constexpr int SBd = 132;
  constexpr int SAd = BN + 4;
  constexpr int KSTEPS = KC / 8;

  extern __shared__ uint32_t smu[];
  uint32_t* sB = smu;
  float* sA = (float*)(smu + KC * SBd);
  float* tail = sA + KC * SAd;
  float* mu = tail;
  float* rs = tail + 128;
  float* snw = tail + 256;
  float* snb = tail + 304;
  float* sBf = (float*)sB;

  int tid = threadIdx.x;
  int wid = tid / 32, lane = tid % 32;
  int warp_m = wid % MT, warp_n = wid / MT;
  int n0 = warp_n * 64;
  int pb = blockIdx.y;
  int b = pb / (Np / 128);
  int n0g = (pb % (Np / 128)) * 128;
  int tg = lane & 3, gr = lane >> 2;

  const TIN* ip = in + ((size_t)b * in_cs + in_co) * Np + n0g;
  const float* wp = PBW ? (w + (size_t)b * CO * K) : w;

  float acc[8][4];

  if constexpr (K == KC) {
    for (int i = tid; i < KC * 64; i += NTH) {
      int k = i >> 6, j2 = i & 63;
      float2 f;
      if constexpr (sizeof(TIN) == 2)
        f = __half22float2(
            *reinterpret_cast<const __half2*>(ip + (size_t)k * Np + 2 * j2));
      else
        f = *reinterpret_cast<const float2*>(ip + (size_t)k * Np + 2 * j2);
      sBf[k * SBd + 2 * j2] = f.x;
      sBf[k * SBd + 2 * j2 + 1] = f.y;
    }
    if constexpr (LN) {
      for (int i = tid; i < K; i += NTH) {
        snw[i] = nw[i];
        snb[i] = nb[i];
      }
      __syncthreads();
      for (int j = tid; j < 128; j += NTH) {
        float s = 0.f, s2 = 0.f;
#pragma unroll 8
        for (int k = 0; k < K; k++) {
          float xv = sBf[k * SBd + j];
          s += xv;
          s2 = fmaf(xv, xv, s2);
        }
        float m = s * (1.f / (float)K);
        float v = fmaxf(s2 * (1.f / (float)K) - m * m, 0.f);
        mu[j] = m;
        rs[j] = rsqrtf(v + 1e-5f);
      }
      __syncthreads();
      for (int i = tid; i < KC * 128; i += NTH) {
        int k = i >> 7, j = i & 127;
        sB[k * SBd + j] =
            f2tf((sBf[k * SBd + j] - mu[j]) * rs[j] * snw[k] + snb[k]);
      }
    }
    __syncthreads();

#pragma unroll
    for (int ct = 0; ct < COT; ct++) {
      int o0 = ct * BN;
      // coalesced A staging: consecutive threads read consecutive k
      for (int i = tid; i < KC * BN; i += NTH) {
        int k = i % KC, m = i / KC;
        int o = o0 + m;
        sA[k * SAd + m] = (o < CO) ? wp[(size_t)o * K + k] : 0.f;
      }
      __syncthreads();
#pragma unroll
      for (int j = 0; j < 8; j++)
#pragma unroll
        for (int i = 0; i < 4; i++) acc[j][i] = 0.f;
#pragma unroll
      for (int ks = 0; ks < KSTEPS; ks++) {
        int kr0 = ks * 8 + tg;
        uint32_t ah0 = f2tf(sA[kr0 * SAd + warp_m * 16 + gr]);
        uint32_t ah1 = f2tf(sA[kr0 * SAd + warp_m * 16 + gr + 8]);
        uint32_t ah2 = f2tf(sA[(kr0 + 4) * SAd + warp_m * 16 + gr]);
        uint32_t ah3 = f2tf(sA[(kr0 + 4) * SAd + warp_m * 16 + gr + 8]);
#pragma unroll
        for (int j = 0; j < 8; j++) {
          uint32_t b0 = sB[kr0 * SBd + n0 + j * 8 + gr];
          uint32_t b1 = sB[(kr0 + 4) * SBd + n0 + j * 8 + gr];
          mma_tf32(acc[j], ah0, ah1, ah2, ah3, b0, b1);
        }
      }
#pragma unroll
      for (int j = 0; j < 8; j++) {
        int nn = n0 + j * 8 + 2 * tg;
#pragma unroll
        for (int h = 0; h < 2; h++) {
          int o = o0 + warp_m * 16 + gr + h * 8;
          if (o < CO) {
            float2 r = make_float2(acc[j][h * 2], acc[j][h * 2 + 1]);
            if constexpr (RES) {
              const TRES* rp = res + ((size_t)b * res_cs + o) * Np + n0g + nn;
              float2 q;
              if constexpr (sizeof(TRES) == 2)
                q = __half22float2(*reinterpret_cast<const __half2*>(rp));
              else
                q = *reinterpret_cast<const float2*>(rp);
              r.x += q.x;
              r.y += q.y;
            }
            if constexpr (sizeof(TOUT) == 2)
              *reinterpret_cast<__half2*>(out + ((size_t)b * out_cs + o) * Np +
                                          n0g + nn) =
                  __floats2half2_rn(r.x, r.y);
            else
              *reinterpret_cast<float2*>(out + ((size_t)b * out_cs + o) * Np +
                                         n0g + nn) = r;
          }
        }
      }
      if (ct + 1 < COT) __syncthreads();
    }
  } else {
#pragma unroll
    for (int j = 0; j < 8; j++)
#pragma unroll
      for (int i = 0; i < 4; i++) acc[j][i] = 0.f;
    for (int k0 = 0; k0 < K; k0 += KC) {
      for (int i = tid; i < KC * BN; i += NTH) {
        int k = i % KC, m = i / KC;
        int o = m, kk = k0 + k;
        sA[k * SAd + m] = (o < CO && kk < K) ? wp[(size_t)o * K + kk] : 0.f;
      }
      for (int i = tid; i < KC * 64; i += NTH) {
        int k = i >> 6, j2 = i & 63;
        int kk = k0 + k;
        float2 f = make_float2(0.f, 0.f);
        if (kk < K)
          f = __half22float2(
              *reinterpret_cast<const __half2*>(ip + (size_t)kk * Np + 2 * j2));
        sBf[k * SBd + 2 * j2] = f.x;
        sBf[k * SBd + 2 * j2 + 1] = f.y;
      }
      __syncthreads();
#pragma unroll
      for (int ks = 0; ks < KSTEPS; ks++) {
        int kr0 = ks * 8 + tg;
        uint32_t ah0 = f2tf(sA[kr0 * SAd + warp_m * 16 + gr]);
        uint32_t ah1 = f2tf(sA[kr0 * SAd + warp_m * 16 + gr + 8]);
        uint32_t ah2 = f2tf(sA[(kr0 + 4) * SAd + warp_m * 16 + gr]);
        uint32_t ah3 = f2tf(sA[(kr0 + 4) * SAd + warp_m * 16 + gr + 8]);
#pragma unroll
        for (int j = 0; j < 8; j++) {
          uint32_t b0 = sB[kr0 * SBd + n0 + j * 8 + gr];
          uint32_t b1 = sB[(kr0 + 4) * SBd + n0 + j * 8 + gr];
          mma_tf32(acc[j], ah0, ah1, ah2, ah3, b0, b1);
        }
      }
      if (k0 + KC < K) __syncthreads();
    }
#pragma unroll
    for (int j = 0; j < 8; j++) {
      int nn = n0 + j * 8 + 2 * tg;
#pragma unroll
      for (int h = 0; h < 2; h++) {
        int o = warp_m * 16 + gr + h * 8;
        if (o < CO) {
          float2 r = make_float2(acc[j][h * 2], acc[j][h * 2 + 1]);
          if constexpr (RES) {
            const TRES* rp = res + ((size_t)b * res_cs + o) * Np + n0g + nn;
            float2 q;
            if constexpr (sizeof(TRES) == 2)
              q = __half22float2(*reinterpret_cast<const __half2*>(rp));
            else
              q = *reinterpret_cast<const float2*>(rp);
            r.x += q.x;
            r.y += q.y;
          }
          if constexpr (sizeof(TOUT) == 2)
            *reinterpret_cast<__half2*>(out + ((size_t)b * out_cs + o) * Np +
                                        n0g + nn) = __floats2half2_rn(r.x, r.y);
          else
            *reinterpret_cast<float2*>(out + ((size_t)b * out_cs + o) * Np +
                                       n0g + nn) = r;
        }
      }
    }
  }
}

// ---------------------------------------------------------------------------
// Depthwise 3x3 conv (SAME) on channels [c0, c0+Cn) of a C3-stride buffer,
// fp16 in/out, 16 px per thread (MLP 6).
// ---------------------------------------------------------------------------
__global__ __launch_bounds__(256) void k_dw(const __half* __restrict__ in,
                                            const float* __restrict__ w9,
                                            __half* __restrict__ out, int c0,
                                            int Cn) {
  int idx = blockIdx.x * 256 + threadIdx.x;
  int total = Bb * Cn * Hh * (Ww / 16);
  if (idx >= total) return;
  int xq = idx % (Ww / 16);
  int t = idx / (Ww / 16);
  int y = t % Hh; t /= Hh;
  int c = c0 + (t % Cn);
  int b = t / Cn;
  int x0 = xq * 16;

  float wv[9];
#pragma unroll
  for (int i = 0; i < 9; i++) wv[i] = w9[c * 9 + i];

  const __half* base = in + ((size_t)b * C3 + c) * Np;
  float a[16];
#pragma unroll
  for (int p = 0; p < 16; p++) a[p] = 0.f;

#pragma unroll
  for (int dy = 0; dy < 3; dy++) {
    int yy = y + dy - 1;
    if (yy < 0 || yy >= Hh) continue;
    const __half* row = base + (size_t)yy * Ww;
    float v[18];
    v[0] = (x0 > 0) ? __half2float(row[x0 - 1]) : 0.f;
    uint4 m0 = *reinterpret_cast<const uint4*>(row + x0);
    uint4 m1 = *reinterpret_cast<const uint4*>(row + x0 + 8);
    const __half2* h0 = reinterpret_cast<const __half2*>(&m0);
    const __half2* h1 = reinterpret_cast<const __half2*>(&m1);
#pragma unroll
    for (int q = 0; q < 4; q++) {
      float2 f0 = __half22float2(h0[q]);
      float2 f1 = __half22float2(h1[q]);
      v[1 + 2 * q] = f0.x;
      v[2 + 2 * q] = f0.y;
      v[9 + 2 * q] = f1.x;
      v[10 + 2 * q] = f1.y;
    }
    v[17] = (x0 + 16 < Ww) ? __half2float(row[x0 + 16]) : 0.f;
#pragma unroll
    for (int dx = 0; dx < 3; dx++) {
      float wt = wv[dy * 3 + dx];
#pragma unroll
      for (int p = 0; p < 16; p++) a[p] = fmaf(v[dx + p], wt, a[p]);
    }
  }
  __half2 o8[8];
#pragma unroll
  for (int q = 0; q < 8; q++) o8[q] = __floats2half2_rn(a[2 * q], a[2 * q + 1]);
  __half* op = out + ((size_t)b * C3 + c) * Np + (size_t)y * Ww + x0;
  *reinterpret_cast<uint4*>(op) = *reinterpret_cast<uint4*>(o8);
  *reinterpret_cast<uint4*>(op + 8) = *reinterpret_cast<uint4*>(o8 + 4);
}

// ---------------------------------------------------------------------------
// GDFN: depthwise 3x3 on channels c and c+127, gelu gate; 16 px per thread.
// ---------------------------------------------------------------------------
__global__ __launch_bounds__(128) void k_dwgelu(const __half* __restrict__ in,
                                                const float* __restrict__ w9,
                                                __half* __restrict__ out) {
  int idx = blockIdx.x * 128 + threadIdx.x;
  int total = Bb * HID * Hh * (Ww / 16);
  if (idx >= total) return;
  int xq = idx % (Ww / 16);
  int t = idx / (Ww / 16);
  int y = t % Hh; t /= Hh;
  int c = t % HID;
  int b = t / HID;
  int x0 = xq * 16;

  float w1[9], w2[9];
#pragma unroll
  for (int i = 0; i < 9; i++) {
    w1[i] = w9[c * 9 + i];
    w2[i] = w9[(c + HID) * 9 + i];
  }
  const __half* b1 = in + ((size_t)b * HID2 + c) * Np;
  const __half* b2 = in + ((size_t)b * HID2 + c + HID) * Np;
  float a1[16], a2[16];
#pragma unroll
  for (int p = 0; p < 16; p++) {
    a1[p] = 0.f;
    a2[p] = 0.f;
  }
#pragma unroll
  for (int dy = 0; dy < 3; dy++) {
    int yy = y + dy - 1;
    if (yy < 0 || yy >= Hh) continue;
    const __half* r1 = b1 + (size_t)yy * Ww;
    const __half* r2 = b2 + (size_t)yy * Ww;
    float v1[18], v2[18];
    v1[0] = (x0 > 0) ? __half2float(r1[x0 - 1]) : 0.f;
    v2[0] = (x0 > 0) ? __half2float(r2[x0 - 1]) : 0.f;
    uint4 ma0 = *reinterpret_cast<const uint4*>(r1 + x0);
    uint4 ma1 = *reinterpret_cast<const uint4*>(r1 + x0 + 8);
    uint4 mb0 = *reinterpret_cast<const uint4*>(r2 + x0);
    uint4 mb1 = *reinterpret_cast<const uint4*>(r2 + x0 + 8);
    const __half2* ha0 = reinterpret_cast<const __half2*>(&ma0);
    const __half2* ha1 = reinterpret_cast<const __half2*>(&ma1);
    const __half2* hb0 = reinterpret_cast<const __half2*>(&mb0);
    const __half2* hb1 = reinterpret_cast<const __half2*>(&mb1);
#pragma unroll
    for (int q = 0; q < 4; q++) {
      float2 fa0 = __half22float2(ha0[q]);
      float2 fa1 = __half22float2(ha1[q]);
      float2 fb0 = __half22float2(hb0[q]);
      float2 fb1 = __half22float2(hb1[q]);
      v1[1 + 2 * q] = fa0.x;
      v1[2 + 2 * q] = fa0.y;
      v1[9 + 2 * q] = fa1.x;
      v1[10 + 2 * q] = fa1.y;
      v2[1 + 2 * q] = fb0.x;
      v2[2 + 2 * q] = fb0.y;
      v2[9 + 2 * q] = fb1.x;
      v2[10 + 2 * q] = fb1.y;
    }
    v1[17] = (x0 + 16 < Ww) ? __half2float(r1[x0 + 16]) : 0.f;
    v2[17] = (x0 + 16 < Ww) ? __half2float(r2[x0 + 16]) : 0.f;
#pragma unroll
    for (int dx = 0; dx < 3; dx++) {
      float wa = w1[dy * 3 + dx], wb = w2[dy * 3 + dx];
#pragma unroll
      for (int p = 0; p < 16; p++) {
        a1[p] = fmaf(v1[dx + p], wa, a1[p]);
        a2[p] = fmaf(v2[dx + p], wb, a2[p]);
      }
    }
  }
  __half2 o8[8];
#pragma unroll
  for (int q = 0; q < 8; q++) {
    float u0 = a1[2 * q], u1 = a1[2 * q + 1];
    float g0 = 0.5f * u0 * (1.f + erff(u0 * 0.70710678118654752f)) * a2[2 * q];
    float g1 =
        0.5f * u1 * (1.f + erff(u1 * 0.70710678118654752f)) * a2[2 * q + 1];
    o8[q] = __floats2half2_rn(g0, g1);
  }
  __half* op = out + ((size_t)b * HID + c) * Np + (size_t)y * Ww + x0;
  *reinterpret_cast<uint4*>(op) = *reinterpret_cast<uint4*>(o8);
  *reinterpret_cast<uint4*>(op + 8) = *reinterpret_cast<uint4*>(o8 + 4);
}

// ---------------------------------------------------------------------------
// Gram partials via tensor cores (round-12 proven).
// ---------------------------------------------------------------------------
__global__ __launch_bounds__(192) void k_gram(const __half* __restrict__ qkv,
                                              float* __restrict__ part) {
  constexpr int PS = 36;
  constexpr int BUF = 48 * PS;
  __shared__ uint32_t sQb[2 * BUF];
  __shared__ uint32_t sKb[2 * BUF];
  __shared__ float sN[192];

  int blk = blockIdx.x;
  int b = blk / NPART, pc = blk % NPART;
  int n0 = pc * CHUNK;
  const __half* q = qkv + (size_t)b * C3 * Np;
  const __half* k = q + (size_t)48 * Np;

  int tid = threadIdx.x;
  int wid = tid / 32, lane = tid % 32;
  int tg = lane & 3, gr = lane >> 2;
  int m0 = (wid % 3) * 16;
  int nb = (wid / 3) * 24;

  float acc[3][4];
#pragma unroll
  for (int jt = 0; jt < 3; jt++)
#pragma unroll
    for (int i = 0; i < 4; i++) acc[jt][i] = 0.f;
  float nrm = 0.f;
  int nc = tid % 96, nh = tid / 96;

  auto stage = [&](int sub, int buf) {
    int off = n0 + sub * 32;
    float2* dQ = reinterpret_cast<float2*>(sQb + buf * BUF);
    float2* dK = reinterpret_cast<float2*>(sKb + buf * BUF);
    for (int i = tid; i < 48 * 16; i += 192) {
      int c = i >> 4, j2 = i & 15;
      float2 fq = __half22float2(
          *reinterpret_cast<const __half2*>(q + (size_t)c * Np + off + 2 * j2));
      float2 fk = __half22float2(
          *reinterpret_cast<const __half2*>(k + (size_t)c * Np + off + 2 * j2));
      dQ[c * (PS / 2) + j2] = fq;
      dK[c * (PS / 2) + j2] = fk;
    }
  };

  stage(0, 0);
  __syncthreads();

  constexpr int NSUB = CHUNK / 32;  // 16
  for (int sub = 0; sub < NSUB; sub++) {
    int cur = sub & 1;
    if (sub < NSUB - 1) stage(sub + 1, cur ^ 1);
    uint32_t* sQ = sQb + cur * BUF;
    uint32_t* sK = sKb + cur * BUF;
#pragma unroll
    for (int ks = 0; ks < 4; ks++) {
      int kr0 = ks * 8 + tg;
      uint32_t a0 = sQ[(m0 + gr) * PS + kr0];
      uint32_t a1 = sQ[(m0 + gr + 8) * PS + kr0];
      uint32_t a2 = sQ[(m0 + gr) * PS + kr0 + 4];
      uint32_t a3 = sQ[(m0 + gr + 8) * PS + kr0 + 4];
#pragma unroll
      for (int jt = 0; jt < 3; jt++) {
        uint32_t b0 = sK[(nb + jt * 8 + gr) * PS + kr0];
        uint32_t b1 = sK[(nb + jt * 8 + gr) * PS + kr0 + 4];
        mma_tf32(acc[jt], a0, a1, a2, a3, b0, b1);
      }
    }
    {
      const float2* s2 = (nc < 48)
                             ? (reinterpret_cast<const float2*>(sQ) +
                                nc * (PS / 2))
                             : (reinterpret_cast<const float2*>(sK) +
                                (nc - 48) * (PS / 2));
#pragma unroll
      for (int j2 = nh * 8; j2 < nh * 8 + 8; j2++) {
        float2 v = s2[j2];
        nrm = fmaf(v.x, v.x, fmaf(v.y, v.y, nrm));
      }
    }
    __syncthreads();
  }

  sN[tid] = nrm;
  __syncthreads();
  float* pp = part + (size_t)blk * GSLOTS;
#pragma unroll
  for (int jt = 0; jt < 3; jt++) {
    int col = nb + jt * 8 + 2 * tg;
    pp[(m0 + gr) * 48 + col] = acc[jt][0];
    pp[(m0 + gr) * 48 + col + 1] = acc[jt][1];
    pp[(m0 + gr + 8) * 48 + col] = acc[jt][2];
    pp[(m0 + gr + 8) * 48 + col + 1] = acc[jt][3];
  }
  if (tid < 96) pp[2304 + tid] = sN[tid] + sN[tid + 96];
}

__global__ void k_red(const float* __restrict__ part, float* __restrict__ gfin) {
  int s = blockIdx.x * blockDim.x + threadIdx.x;
  if (s >= Bb * GSLOTS) return;
  int b = s / GSLOTS, slot = s % GSLOTS;
  const float* p = part + (size_t)b * NPART * GSLOTS + slot;
  float a0 = 0.f, a1 = 0.f, a2 = 0.f, a3 = 0.f;
  for (int i = 0; i < NPART; i += 4) {
    a0 += p[(size_t)(i + 0) * GSLOTS];
    a1 += p[(size_t)(i + 1) * GSLOTS];
    a2 += p[(size_t)(i + 2) * GSLOTS];
    a3 += p[(size_t)(i + 3) * GSLOTS];
  }
  gfin[s] = (a0 + a1) + (a2 + a3);
}

__global__ __launch_bounds__(256) void k_att(const float* __restrict__ gfin,
                                             const float* __restrict__ temp,
                                             const float* __restrict__ po,
                                             float* __restrict__ M) {
  __shared__ float sG[2304];
  __shared__ float sAt[2304];
  __shared__ float snq[48], snk[48];
  int b = blockIdx.x, tid = threadIdx.x;
  const float* g = gfin + (size_t)b * GSLOTS;
  for (int i = tid; i < 2304; i += 256) sG[i] = g[i];
  if (tid < 96) {
    float nv = sqrtf(fmaxf(g[2304 + tid], 0.f));
    nv = fmaxf(nv, 1e-12f);
    if (tid < 48) snq[tid] = nv;
    else snk[tid - 48] = nv;
  }
  __syncthreads();
  float tv = temp[0];
  for (int i = tid; i < 2304; i += 256) {
    int c = i / 48, d = i % 48;
    sG[i] = sG[i] * tv / (snq[c] * snk[d]);
  }
  __syncthreads();
  if (tid < 48) {
    float mx = -1e30f;
    for (int d = 0; d < 48; d++) mx = fmaxf(mx, sG[tid * 48 + d]);
    float s = 0.f;
    for (int d = 0; d < 48; d++) {
      float e = expf(sG[tid * 48 + d] - mx);
      sAt[tid * 48 + d] = e;
      s += e;
    }
    float inv = 1.f / s;
    for (int d = 0; d < 48; d++) sAt[tid * 48 + d] *= inv;
  }
  __syncthreads();
  for (int i = tid; i < 2304; i += 256) {
    int o = i / 48, d = i % 48;
    float a = 0.f;
#pragma unroll 8
    for (int c = 0; c < 48; c++) a = fmaf(po[o * 48 + c], sAt[c * 48 + d], a);
    M[(size_t)b * 2304 + i] = a;
  }
}

// ---------------------------------------------------------------------------
// Launch (dw_v forked onto side stream; round-14 structure)
// ---------------------------------------------------------------------------
extern "C" void kernel_launch(void* const* d_in, const int* in_sizes, int n_in,
                              void* d_out, int out_size) {
  (void)in_sizes; (void)n_in; (void)out_size;
  const float* x      = (const float*)d_in[0];
  const float* pe_w   = (const float*)d_in[1];
  const float* n1_w   = (const float*)d_in[2];
  const float* n1_b   = (const float*)d_in[3];
  const float* temp   = (const float*)d_in[4];
  const float* qkv_w  = (const float*)d_in[5];
  const float* qkv_dw = (const float*)d_in[6];
  const float* po_w   = (const float*)d_in[7];
  const float* n2_w   = (const float*)d_in[8];
  const float* n2_b   = (const float*)d_in[9];
  const float* pi_w   = (const float*)d_in[10];
  const float* ffn_dw = (const float*)d_in[11];
  const float* fo_w   = (const float*)d_in[12];
  float* out = (float*)d_out;

  float *patch, *first, *part, *gfin, *M;
  __half *qkv0, *qkv, *hbuf, *gate;
  cudaGetSymbolAddress((void**)&patch, g_patch);
  cudaGetSymbolAddress((void**)&qkv0,  g_qkv0);
  cudaGetSymbolAddress((void**)&qkv,   g_qkv);
  cudaGetSymbolAddress((void**)&first, g_first);
  cudaGetSymbolAddress((void**)&hbuf,  g_hbuf);
  cudaGetSymbolAddress((void**)&gate,  g_gate);
  cudaGetSymbolAddress((void**)&part,  g_part);
  cudaGetSymbolAddress((void**)&gfin,  g_gfin);
  cudaGetSymbolAddress((void**)&M,     g_M);

  constexpr int SM_T48 = (48 * 132 + 48 * 52 + 352) * 4;   // 36736
  constexpr int SM_PI  = (48 * 132 + 48 * 68 + 352) * 4;   // 39808
  constexpr int SM_FO  = (64 * 132 + 64 * 52 + 352) * 4;   // 48512

  static cudaStream_t s2 = nullptr;
  static cudaEvent_t evFork = nullptr, evJoin = nullptr;
  if (s2 == nullptr) {
    cudaStreamCreateWithFlags(&s2, cudaStreamNonBlocking);
    cudaEventCreateWithFlags(&evFork, cudaEventDisableTiming);
    cudaEventCreateWithFlags(&evJoin, cudaEventDisableTiming);
    cudaFuncSetAttribute(
        k_tgemm<127, 64, 48, 1, false, true, false, __half, float, float>,
        cudaFuncAttributeMaxDynamicSharedMemorySize, SM_FO);
  }

  int gpix = Bb * Np / 128;  // 4096 pixel-tiles

  // 1. patch embed (fp32)
  k_pe<<<Bb * Hh, 128>>>(x, pe_w, patch);

  // 2. LN(patch) -> qkv 1x1 (48 -> 144), fp16 out; 3 CO-tiles per block
  k_tgemm<48, 48, 48, 3, true, false, false, float, float, __half>
      <<<dim3(1, gpix), 192, SM_T48>>>(patch, Cc, 0, qkv_w, n1_w, n1_b,
                                       nullptr, 0, qkv0, C3, C3);

  // fork: dw on v-channels runs concurrently with dw_qk + gram chain
  cudaEventRecord(evFork, 0);
  cudaStreamWaitEvent(s2, evFork, 0);
  k_dw<<<(Bb * 48 * Hh * (Ww / 16) + 255) / 256, 256, 0, s2>>>(
      qkv0, qkv_dw, qkv, 96, 48);
  cudaEventRecord(evJoin, s2);

  // 3. depthwise 3x3 on q,k channels (stream 0)
  k_dw<<<(Bb * 96 * Hh * (Ww / 16) + 255) / 256, 256>>>(qkv0, qkv_dw, qkv, 0,
                                                        96);

  // 4-6. gram -> reduce -> softmax + fold po_w into M
  k_gram<<<Bb * NPART, 192>>>(qkv, part);
  k_red<<<(Bb * GSLOTS + 255) / 256, 256>>>(part, gfin);
  k_att<<<Bb, 256>>>(gfin, temp, po_w, M);

  // join: attn-v GEMM needs dw'd v
  cudaStreamWaitEvent((cudaStream_t)0, evJoin, 0);

  // 7. first = patch + M @ v
  k_tgemm<48, 48, 48, 1, false, true, true, __half, float, float>
      <<<dim3(1, gpix), 192, SM_T48>>>(qkv, C3, 96, M, nullptr, nullptr, patch,
                                       Cc, first, Cc, Cc);

  // 8. LN(first) -> pi 1x1 (48 -> 254), fp16 out; 4 CO-tiles per block
  k_tgemm<48, 48, 64, 4, true, false, false, float, float, __half>
      <<<dim3(1, gpix), 256, SM_PI>>>(first, Cc, 0, pi_w, n2_w, n2_b, nullptr,
                                      0, hbuf, HID2, HID2);

  // 9. depthwise 3x3 + exact-gelu gating (254 -> 127), fp16, 16 px/thread
  k_dwgelu<<<(Bb * HID * Hh * (Ww / 16) + 127) / 128, 128>>>(hbuf, ffn_dw,
                                                             gate);

  // 10. out = first + fo 1x1 (127 -> 48), fp32 out
  k_tgemm<127, 64, 48, 1, false, true, false, __half, float, float>
      <<<dim3(1, gpix), 192, SM_FO>>>(gate, HID, 0, fo_w, nullptr, nullptr,
                                      first, Cc, out, Cc, Cc);
}

// round 17
// speedup vs baseline: 1.4050x; 1.0192x over previous
#include <cuda_runtime.h>
#include <cuda_fp16.h>
#include <math.h>
#include <stdint.h>

// ---------------------------------------------------------------------------
// Problem constants
// ---------------------------------------------------------------------------
namespace {
constexpr int Bb   = 2;
constexpr int Hh   = 512;
constexpr int Ww   = 512;
constexpr int Np   = Hh * Ww;
constexpr int Cc   = 48;
constexpr int C3   = 144;
constexpr int HID  = 127;
constexpr int HID2 = 254;
constexpr int NPART  = 512;
constexpr int CHUNK  = Np / NPART;   // 512
constexpr int GSLOTS = 48 * 48 + 96;
}

// ---------------------------------------------------------------------------
// Scratch (all large intermediates fp16; fp32 only for gram partials / M)
// ---------------------------------------------------------------------------
__device__ __half g_patch[(size_t)Bb * Cc * Np];
__device__ __half g_qkv0 [(size_t)Bb * C3 * Np];
__device__ __half g_qkv  [(size_t)Bb * C3 * Np];
__device__ __half g_first[(size_t)Bb * Cc * Np];
__device__ __half g_hbuf [(size_t)Bb * HID2 * Np];
__device__ __half g_gate [(size_t)Bb * HID * Np];
__device__ float  g_part [(size_t)Bb * NPART * GSLOTS];
__device__ float  g_gfin [Bb * GSLOTS];
__device__ float  g_M    [Bb * 48 * 48];

// ---------------------------------------------------------------------------
// tf32 helpers
// ---------------------------------------------------------------------------
__device__ __forceinline__ uint32_t f2tf(float f) {
  uint32_t r;
  asm("cvt.rna.tf32.f32 %0, %1;" : "=r"(r) : "f"(f));
  return r;
}
__device__ __forceinline__ void mma_tf32(float c[4], uint32_t a0, uint32_t a1,
                                         uint32_t a2, uint32_t a3, uint32_t b0,
                                         uint32_t b1) {
  asm volatile(
      "mma.sync.aligned.m16n8k8.row.col.f32.tf32.tf32.f32 "
      "{%0,%1,%2,%3}, {%4,%5,%6,%7}, {%8,%9}, {%0,%1,%2,%3};"
      : "+f"(c[0]), "+f"(c[1]), "+f"(c[2]), "+f"(c[3])
      : "r"(a0), "r"(a1), "r"(a2), "r"(a3), "r"(b0), "r"(b1));
}

// ---------------------------------------------------------------------------
// K1: patch embed conv 3x3, 3 -> 48 (fp32 math, fp16 out)
// ---------------------------------------------------------------------------
__global__ __launch_bounds__(128) void k_pe(const float* __restrict__ x,
                                            const float* __restrict__ pw,
                                            __half* __restrict__ out) {
  __shared__ float ws[48 * 27];
  __shared__ float si[3][3][514];
  int b = blockIdx.x / Hh, y = blockIdx.x % Hh;
  int tid = threadIdx.x;
  for (int i = tid; i < 48 * 27; i += 128) ws[i] = pw[i];
  for (int i = tid; i < 3 * 3 * 512; i += 128) {
    int ch = i / 1536, r = (i / 512) % 3, xx = i % 512;
    int yy = y - 1 + r;
    float v = (yy >= 0 && yy < Hh)
                  ? x[((size_t)(b * 3 + ch) * Hh + yy) * Ww + xx]
                  : 0.f;
    si[ch][r][xx + 1] = v;
  }
  if (tid < 9) {
    int ch = tid / 3, r = tid % 3;
    si[ch][r][0] = 0.f;
    si[ch][r][513] = 0.f;
  }
  __syncthreads();

  int x0 = tid * 4;
  float rv[3][3][6];
#pragma unroll
  for (int ch = 0; ch < 3; ch++)
#pragma unroll
    for (int r = 0; r < 3; r++)
#pragma unroll
      for (int d = 0; d < 6; d++) rv[ch][r][d] = si[ch][r][x0 + d];

  __half* op = out + (size_t)b * Cc * Np + (size_t)y * Ww + x0;
  for (int o = 0; o < 48; o++) {
    float a0 = 0.f, a1 = 0.f, a2 = 0.f, a3 = 0.f;
#pragma unroll
    for (int ch = 0; ch < 3; ch++)
#pragma unroll
      for (int r = 0; r < 3; r++)
#pragma unroll
        for (int dx = 0; dx < 3; dx++) {
          float w = ws[o * 27 + ch * 9 + r * 3 + dx];
          a0 = fmaf(rv[ch][r][dx + 0], w, a0);
          a1 = fmaf(rv[ch][r][dx + 1], w, a1);
          a2 = fmaf(rv[ch][r][dx + 2], w, a2);
          a3 = fmaf(rv[ch][r][dx + 3], w, a3);
        }
    __half2 h0 = __floats2half2_rn(a0, a1);
    __half2 h1 = __floats2half2_rn(a2, a3);
    uint2 pk = make_uint2(*reinterpret_cast<uint32_t*>(&h0),
                          *reinterpret_cast<uint32_t*>(&h1));
    *reinterpret_cast<uint2*>(op + (size_t)o * Np) = pk;
  }
}

// ---------------------------------------------------------------------------
// Tensor-core pixel GEMM, single-pass tf32, smem A-tile with COALESCED
// staging (round-16 proven).
// ---------------------------------------------------------------------------
template <int K, int KC, int BN, int COT, bool LN, bool RES, bool PBW,
          typename TIN, typename TRES, typename TOUT>
__global__ __launch_bounds__((BN / 16) * 64) void k_tgemm(
    const TIN* __restrict__ in, int in_cs, int in_co,
    const float* __restrict__ w, const float* __restrict__ nw,
    const float* __restrict__ nb, const TRES* __restrict__ res, int res_cs,
    TOUT* __restrict__ out, int out_cs, int CO) {
  static_assert(!LN || K == KC, "LN needs single chunk");
  static_assert(COT == 1 || K == KC, "COT>1 needs single chunk");
  constexpr int MT = BN / 16;
  constexpr int NTH = MT * 64;
  constexpr int SBd = 132;
  constexpr int SAd = BN + 4;
  constexpr int KSTEPS = KC / 8;

  extern __shared__ uint32_t smu[];
  uint32_t* sB = smu;
  float* sA = (float*)(smu + KC * SBd);
  float* tail = sA + KC * SAd;
  float* mu = tail;
  float* rs = tail + 128;
  float* snw = tail + 256;
  float* snb = tail + 304;
  float* sBf = (float*)sB;

  int tid = threadIdx.x;
  int wid = tid / 32, lane = tid % 32;
  int warp_m = wid % MT, warp_n = wid / MT;
  int n0 = warp_n * 64;
  int pb = blockIdx.y;
  int b = pb / (Np / 128);
  int n0g = (pb % (Np / 128)) * 128;
  int tg = lane & 3, gr = lane >> 2;

  const TIN* ip = in + ((size_t)b * in_cs + in_co) * Np + n0g;
  const float* wp = PBW ? (w + (size_t)b * CO * K) : w;

  float acc[8][4];

  if constexpr (K == KC) {
    for (int i = tid; i < KC * 64; i += NTH) {
      int k = i >> 6, j2 = i & 63;
      float2 f;
      if constexpr (sizeof(TIN) == 2)
        f = __half22float2(
            *reinterpret_cast<const __half2*>(ip + (size_t)k * Np + 2 * j2));
      else
        f = *reinterpret_cast<const float2*>(ip + (size_t)k * Np + 2 * j2);
      sBf[k * SBd + 2 * j2] = f.x;
      sBf[k * SBd + 2 * j2 + 1] = f.y;
    }
    if constexpr (LN) {
      for (int i = tid; i < K; i += NTH) {
        snw[i] = nw[i];
        snb[i] = nb[i];
      }
      __syncthreads();
      for (int j = tid; j < 128; j += NTH) {
        float s = 0.f, s2 = 0.f;
#pragma unroll 8
        for (int k = 0; k < K; k++) {
          float xv = sBf[k * SBd + j];
          s += xv;
          s2 = fmaf(xv, xv, s2);
        }
        float m = s * (1.f / (float)K);
        float v = fmaxf(s2 * (1.f / (float)K) - m * m, 0.f);
        mu[j] = m;
        rs[j] = rsqrtf(v + 1e-5f);
      }
      __syncthreads();
      for (int i = tid; i < KC * 128; i += NTH) {
        int k = i >> 7, j = i & 127;
        sB[k * SBd + j] =
            f2tf((sBf[k * SBd + j] - mu[j]) * rs[j] * snw[k] + snb[k]);
      }
    }
    __syncthreads();

#pragma unroll
    for (int ct = 0; ct < COT; ct++) {
      int o0 = ct * BN;
      // coalesced A staging: consecutive threads read consecutive k
      for (int i = tid; i < KC * BN; i += NTH) {
        int k = i % KC, m = i / KC;
        int o = o0 + m;
        sA[k * SAd + m] = (o < CO) ? wp[(size_t)o * K + k] : 0.f;
      }
      __syncthreads();
#pragma unroll
      for (int j = 0; j < 8; j++)
#pragma unroll
        for (int i = 0; i < 4; i++) acc[j][i] = 0.f;
#pragma unroll
      for (int ks = 0; ks < KSTEPS; ks++) {
        int kr0 = ks * 8 + tg;
        uint32_t ah0 = f2tf(sA[kr0 * SAd + warp_m * 16 + gr]);
        uint32_t ah1 = f2tf(sA[kr0 * SAd + warp_m * 16 + gr + 8]);
        uint32_t ah2 = f2tf(sA[(kr0 + 4) * SAd + warp_m * 16 + gr]);
        uint32_t ah3 = f2tf(sA[(kr0 + 4) * SAd + warp_m * 16 + gr + 8]);
#pragma unroll
        for (int j = 0; j < 8; j++) {
          uint32_t b0 = sB[kr0 * SBd + n0 + j * 8 + gr];
          uint32_t b1 = sB[(kr0 + 4) * SBd + n0 + j * 8 + gr];
          mma_tf32(acc[j], ah0, ah1, ah2, ah3, b0, b1);
        }
      }
#pragma unroll
      for (int j = 0; j < 8; j++) {
        int nn = n0 + j * 8 + 2 * tg;
#pragma unroll
        for (int h = 0; h < 2; h++) {
          int o = o0 + warp_m * 16 + gr + h * 8;
          if (o < CO) {
            float2 r = make_float2(acc[j][h * 2], acc[j][h * 2 + 1]);
            if constexpr (RES) {
              const TRES* rp = res + ((size_t)b * res_cs + o) * Np + n0g + nn;
              float2 q;
              if constexpr (sizeof(TRES) == 2)
                q = __half22float2(*reinterpret_cast<const __half2*>(rp));
              else
                q = *reinterpret_cast<const float2*>(rp);
              r.x += q.x;
              r.y += q.y;
            }
            if constexpr (sizeof(TOUT) == 2)
              *reinterpret_cast<__half2*>(out + ((size_t)b * out_cs + o) * Np +
                                          n0g + nn) =
                  __floats2half2_rn(r.x, r.y);
            else
              *reinterpret_cast<float2*>(out + ((size_t)b * out_cs + o) * Np +
                                         n0g + nn) = r;
          }
        }
      }
      if (ct + 1 < COT) __syncthreads();
    }
  } else {
#pragma unroll
    for (int j = 0; j < 8; j++)
#pragma unroll
      for (int i = 0; i < 4; i++) acc[j][i] = 0.f;
    for (int k0 = 0; k0 < K; k0 += KC) {
      for (int i = tid; i < KC * BN; i += NTH) {
        int k = i % KC, m = i / KC;
        int o = m, kk = k0 + k;
        sA[k * SAd + m] = (o < CO && kk < K) ? wp[(size_t)o * K + kk] : 0.f;
      }
      for (int i = tid; i < KC * 64; i += NTH) {
        int k = i >> 6, j2 = i & 63;
        int kk = k0 + k;
        float2 f = make_float2(0.f, 0.f);
        if (kk < K)
          f = __half22float2(
              *reinterpret_cast<const __half2*>(ip + (size_t)kk * Np + 2 * j2));
        sBf[k * SBd + 2 * j2] = f.x;
        sBf[k * SBd + 2 * j2 + 1] = f.y;
      }
      __syncthreads();
#pragma unroll
      for (int ks = 0; ks < KSTEPS; ks++) {
        int kr0 = ks * 8 + tg;
        uint32_t ah0 = f2tf(sA[kr0 * SAd + warp_m * 16 + gr]);
        uint32_t ah1 = f2tf(sA[kr0 * SAd + warp_m * 16 + gr + 8]);
        uint32_t ah2 = f2tf(sA[(kr0 + 4) * SAd + warp_m * 16 + gr]);
        uint32_t ah3 = f2tf(sA[(kr0 + 4) * SAd + warp_m * 16 + gr + 8]);
#pragma unroll
        for (int j = 0; j < 8; j++) {
          uint32_t b0 = sB[kr0 * SBd + n0 + j * 8 + gr];
          uint32_t b1 = sB[(kr0 + 4) * SBd + n0 + j * 8 + gr];
          mma_tf32(acc[j], ah0, ah1, ah2, ah3, b0, b1);
        }
      }
      if (k0 + KC < K) __syncthreads();
    }
#pragma unroll
    for (int j = 0; j < 8; j++) {
      int nn = n0 + j * 8 + 2 * tg;
#pragma unroll
      for (int h = 0; h < 2; h++) {
        int o = warp_m * 16 + gr + h * 8;
        if (o < CO) {
          float2 r = make_float2(acc[j][h * 2], acc[j][h * 2 + 1]);
          if constexpr (RES) {
            const TRES* rp = res + ((size_t)b * res_cs + o) * Np + n0g + nn;
            float2 q;
            if constexpr (sizeof(TRES) == 2)
              q = __half22float2(*reinterpret_cast<const __half2*>(rp));
            else
              q = *reinterpret_cast<const float2*>(rp);
            r.x += q.x;
            r.y += q.y;
          }
          if constexpr (sizeof(TOUT) == 2)
            *reinterpret_cast<__half2*>(out + ((size_t)b * out_cs + o) * Np +
                                        n0g + nn) = __floats2half2_rn(r.x, r.y);
          else
            *reinterpret_cast<float2*>(out + ((size_t)b * out_cs + o) * Np +
                                       n0g + nn) = r;
        }
      }
    }
  }
}

// ---------------------------------------------------------------------------
// Depthwise 3x3 conv (SAME) on channels [c0, c0+Cn) of a C3-stride buffer,
// fp16 in/out, 16 px per thread (MLP 6).
// ---------------------------------------------------------------------------
__global__ __launch_bounds__(256) void k_dw(const __half* __restrict__ in,
                                            const float* __restrict__ w9,
                                            __half* __restrict__ out, int c0,
                                            int Cn) {
  int idx = blockIdx.x * 256 + threadIdx.x;
  int total = Bb * Cn * Hh * (Ww / 16);
  if (idx >= total) return;
  int xq = idx % (Ww / 16);
  int t = idx / (Ww / 16);
  int y = t % Hh; t /= Hh;
  int c = c0 + (t % Cn);
  int b = t / Cn;
  int x0 = xq * 16;

  float wv[9];
#pragma unroll
  for (int i = 0; i < 9; i++) wv[i] = w9[c * 9 + i];

  const __half* base = in + ((size_t)b * C3 + c) * Np;
  float a[16];
#pragma unroll
  for (int p = 0; p < 16; p++) a[p] = 0.f;

#pragma unroll
  for (int dy = 0; dy < 3; dy++) {
    int yy = y + dy - 1;
    if (yy < 0 || yy >= Hh) continue;
    const __half* row = base + (size_t)yy * Ww;
    float v[18];
    v[0] = (x0 > 0) ? __half2float(row[x0 - 1]) : 0.f;
    uint4 m0 = *reinterpret_cast<const uint4*>(row + x0);
    uint4 m1 = *reinterpret_cast<const uint4*>(row + x0 + 8);
    const __half2* h0 = reinterpret_cast<const __half2*>(&m0);
    const __half2* h1 = reinterpret_cast<const __half2*>(&m1);
#pragma unroll
    for (int q = 0; q < 4; q++) {
      float2 f0 = __half22float2(h0[q]);
      float2 f1 = __half22float2(h1[q]);
      v[1 + 2 * q] = f0.x;
      v[2 + 2 * q] = f0.y;
      v[9 + 2 * q] = f1.x;
      v[10 + 2 * q] = f1.y;
    }
    v[17] = (x0 + 16 < Ww) ? __half2float(row[x0 + 16]) : 0.f;
#pragma unroll
    for (int dx = 0; dx < 3; dx++) {
      float wt = wv[dy * 3 + dx];
#pragma unroll
      for (int p = 0; p < 16; p++) a[p] = fmaf(v[dx + p], wt, a[p]);
    }
  }
  __half2 o8[8];
#pragma unroll
  for (int q = 0; q < 8; q++) o8[q] = __floats2half2_rn(a[2 * q], a[2 * q + 1]);
  __half* op = out + ((size_t)b * C3 + c) * Np + (size_t)y * Ww + x0;
  *reinterpret_cast<uint4*>(op) = *reinterpret_cast<uint4*>(o8);
  *reinterpret_cast<uint4*>(op + 8) = *reinterpret_cast<uint4*>(o8 + 4);
}

// ---------------------------------------------------------------------------
// GDFN: depthwise 3x3 on channels c and c+127, gelu gate; 16 px per thread.
// ---------------------------------------------------------------------------
__global__ __launch_bounds__(128) void k_dwgelu(const __half* __restrict__ in,
                                                const float* __restrict__ w9,
                                                __half* __restrict__ out) {
  int idx = blockIdx.x * 128 + threadIdx.x;
  int total = Bb * HID * Hh * (Ww / 16);
  if (idx >= total) return;
  int xq = idx % (Ww / 16);
  int t = idx / (Ww / 16);
  int y = t % Hh; t /= Hh;
  int c = t % HID;
  int b = t / HID;
  int x0 = xq * 16;

  float w1[9], w2[9];
#pragma unroll
  for (int i = 0; i < 9; i++) {
    w1[i] = w9[c * 9 + i];
    w2[i] = w9[(c + HID) * 9 + i];
  }
  const __half* b1 = in + ((size_t)b * HID2 + c) * Np;
  const __half* b2 = in + ((size_t)b * HID2 + c + HID) * Np;
  float a1[16], a2[16];
#pragma unroll
  for (int p = 0; p < 16; p++) {
    a1[p] = 0.f;
    a2[p] = 0.f;
  }
#pragma unroll
  for (int dy = 0; dy < 3; dy++) {
    int yy = y + dy - 1;
    if (yy < 0 || yy >= Hh) continue;
    const __half* r1 = b1 + (size_t)yy * Ww;
    const __half* r2 = b2 + (size_t)yy * Ww;
    float v1[18], v2[18];
    v1[0] = (x0 > 0) ? __half2float(r1[x0 - 1]) : 0.f;
    v2[0] = (x0 > 0) ? __half2float(r2[x0 - 1]) : 0.f;
    uint4 ma0 = *reinterpret_cast<const uint4*>(r1 + x0);
    uint4 ma1 = *reinterpret_cast<const uint4*>(r1 + x0 + 8);
    uint4 mb0 = *reinterpret_cast<const uint4*>(r2 + x0);
    uint4 mb1 = *reinterpret_cast<const uint4*>(r2 + x0 + 8);
    const __half2* ha0 = reinterpret_cast<const __half2*>(&ma0);
    const __half2* ha1 = reinterpret_cast<const __half2*>(&ma1);
    const __half2* hb0 = reinterpret_cast<const __half2*>(&mb0);
    const __half2* hb1 = reinterpret_cast<const __half2*>(&mb1);
#pragma unroll
    for (int q = 0; q < 4; q++) {
      float2 fa0 = __half22float2(ha0[q]);
      float2 fa1 = __half22float2(ha1[q]);
      float2 fb0 = __half22float2(hb0[q]);
      float2 fb1 = __half22float2(hb1[q]);
      v1[1 + 2 * q] = fa0.x;
      v1[2 + 2 * q] = fa0.y;
      v1[9 + 2 * q] = fa1.x;
      v1[10 + 2 * q] = fa1.y;
      v2[1 + 2 * q] = fb0.x;
      v2[2 + 2 * q] = fb0.y;
      v2[9 + 2 * q] = fb1.x;
      v2[10 + 2 * q] = fb1.y;
    }
    v1[17] = (x0 + 16 < Ww) ? __half2float(r1[x0 + 16]) : 0.f;
    v2[17] = (x0 + 16 < Ww) ? __half2float(r2[x0 + 16]) : 0.f;
#pragma unroll
    for (int dx = 0; dx < 3; dx++) {
      float wa = w1[dy * 3 + dx], wb = w2[dy * 3 + dx];
#pragma unroll
      for (int p = 0; p < 16; p++) {
        a1[p] = fmaf(v1[dx + p], wa, a1[p]);
        a2[p] = fmaf(v2[dx + p], wb, a2[p]);
      }
    }
  }
  __half2 o8[8];
#pragma unroll
  for (int q = 0; q < 8; q++) {
    float u0 = a1[2 * q], u1 = a1[2 * q + 1];
    float g0 = 0.5f * u0 * (1.f + erff(u0 * 0.70710678118654752f)) * a2[2 * q];
    float g1 =
        0.5f * u1 * (1.f + erff(u1 * 0.70710678118654752f)) * a2[2 * q + 1];
    o8[q] = __floats2half2_rn(g0, g1);
  }
  __half* op = out + ((size_t)b * HID + c) * Np + (size_t)y * Ww + x0;
  *reinterpret_cast<uint4*>(op) = *reinterpret_cast<uint4*>(o8);
  *reinterpret_cast<uint4*>(op + 8) = *reinterpret_cast<uint4*>(o8 + 4);
}

// ---------------------------------------------------------------------------
// Gram partials via tensor cores (round-12 proven).
// ---------------------------------------------------------------------------
__global__ __launch_bounds__(192) void k_gram(const __half* __restrict__ qkv,
                                              float* __restrict__ part) {
  constexpr int PS = 36;
  constexpr int BUF = 48 * PS;
  __shared__ uint32_t sQb[2 * BUF];
  __shared__ uint32_t sKb[2 * BUF];
  __shared__ float sN[192];

  int blk = blockIdx.x;
  int b = blk / NPART, pc = blk % NPART;
  int n0 = pc * CHUNK;
  const __half* q = qkv + (size_t)b * C3 * Np;
  const __half* k = q + (size_t)48 * Np;

  int tid = threadIdx.x;
  int wid = tid / 32, lane = tid % 32;
  int tg = lane & 3, gr = lane >> 2;
  int m0 = (wid % 3) * 16;
  int nb = (wid / 3) * 24;

  float acc[3][4];
#pragma unroll
  for (int jt = 0; jt < 3; jt++)
#pragma unroll
    for (int i = 0; i < 4; i++) acc[jt][i] = 0.f;
  float nrm = 0.f;
  int nc = tid % 96, nh = tid / 96;

  auto stage = [&](int sub, int buf) {
    int off = n0 + sub * 32;
    float2* dQ = reinterpret_cast<float2*>(sQb + buf * BUF);
    float2* dK = reinterpret_cast<float2*>(sKb + buf * BUF);
    for (int i = tid; i < 48 * 16; i += 192) {
      int c = i >> 4, j2 = i & 15;
      float2 fq = __half22float2(
          *reinterpret_cast<const __half2*>(q + (size_t)c * Np + off + 2 * j2));
      float2 fk = __half22float2(
          *reinterpret_cast<const __half2*>(k + (size_t)c * Np + off + 2 * j2));
      dQ[c * (PS / 2) + j2] = fq;
      dK[c * (PS / 2) + j2] = fk;
    }
  };

  stage(0, 0);
  __syncthreads();

  constexpr int NSUB = CHUNK / 32;  // 16
  for (int sub = 0; sub < NSUB; sub++) {
    int cur = sub & 1;
    if (sub < NSUB - 1) stage(sub + 1, cur ^ 1);
    uint32_t* sQ = sQb + cur * BUF;
    uint32_t* sK = sKb + cur * BUF;
#pragma unroll
    for (int ks = 0; ks < 4; ks++) {
      int kr0 = ks * 8 + tg;
      uint32_t a0 = sQ[(m0 + gr) * PS + kr0];
      uint32_t a1 = sQ[(m0 + gr + 8) * PS + kr0];
      uint32_t a2 = sQ[(m0 + gr) * PS + kr0 + 4];
      uint32_t a3 = sQ[(m0 + gr + 8) * PS + kr0 + 4];
#pragma unroll
      for (int jt = 0; jt < 3; jt++) {
        uint32_t b0 = sK[(nb + jt * 8 + gr) * PS + kr0];
        uint32_t b1 = sK[(nb + jt * 8 + gr) * PS + kr0 + 4];
        mma_tf32(acc[jt], a0, a1, a2, a3, b0, b1);
      }
    }
    {
      const float2* s2 = (nc < 48)
                             ? (reinterpret_cast<const float2*>(sQ) +
                                nc * (PS / 2))
                             : (reinterpret_cast<const float2*>(sK) +
                                (nc - 48) * (PS / 2));
#pragma unroll
      for (int j2 = nh * 8; j2 < nh * 8 + 8; j2++) {
        float2 v = s2[j2];
        nrm = fmaf(v.x, v.x, fmaf(v.y, v.y, nrm));
      }
    }
    __syncthreads();
  }

  sN[tid] = nrm;
  __syncthreads();
  float* pp = part + (size_t)blk * GSLOTS;
#pragma unroll
  for (int jt = 0; jt < 3; jt++) {
    int col = nb + jt * 8 + 2 * tg;
    pp[(m0 + gr) * 48 + col] = acc[jt][0];
    pp[(m0 + gr) * 48 + col + 1] = acc[jt][1];
    pp[(m0 + gr + 8) * 48 + col] = acc[jt][2];
    pp[(m0 + gr + 8) * 48 + col + 1] = acc[jt][3];
  }
  if (tid < 96) pp[2304 + tid] = sN[tid] + sN[tid + 96];
}

__global__ void k_red(const float* __restrict__ part, float* __restrict__ gfin) {
  int s = blockIdx.x * blockDim.x + threadIdx.x;
  if (s >= Bb * GSLOTS) return;
  int b = s / GSLOTS, slot = s % GSLOTS;
  const float* p = part + (size_t)b * NPART * GSLOTS + slot;
  float a0 = 0.f, a1 = 0.f, a2 = 0.f, a3 = 0.f;
  for (int i = 0; i < NPART; i += 4) {
    a0 += p[(size_t)(i + 0) * GSLOTS];
    a1 += p[(size_t)(i + 1) * GSLOTS];
    a2 += p[(size_t)(i + 2) * GSLOTS];
    a3 += p[(size_t)(i + 3) * GSLOTS];
  }
  gfin[s] = (a0 + a1) + (a2 + a3);
}

__global__ __launch_bounds__(256) void k_att(const float* __restrict__ gfin,
                                             const float* __restrict__ temp,
                                             const float* __restrict__ po,
                                             float* __restrict__ M) {
  __shared__ float sG[2304];
  __shared__ float sAt[2304];
  __shared__ float snq[48], snk[48];
  int b = blockIdx.x, tid = threadIdx.x;
  const float* g = gfin + (size_t)b * GSLOTS;
  for (int i = tid; i < 2304; i += 256) sG[i] = g[i];
  if (tid < 96) {
    float nv = sqrtf(fmaxf(g[2304 + tid], 0.f));
    nv = fmaxf(nv, 1e-12f);
    if (tid < 48) snq[tid] = nv;
    else snk[tid - 48] = nv;
  }
  __syncthreads();
  float tv = temp[0];
  for (int i = tid; i < 2304; i += 256) {
    int c = i / 48, d = i % 48;
    sG[i] = sG[i] * tv / (snq[c] * snk[d]);
  }
  __syncthreads();
  if (tid < 48) {
    float mx = -1e30f;
    for (int d = 0; d < 48; d++) mx = fmaxf(mx, sG[tid * 48 + d]);
    float s = 0.f;
    for (int d = 0; d < 48; d++) {
      float e = expf(sG[tid * 48 + d] - mx);
      sAt[tid * 48 + d] = e;
      s += e;
    }
    float inv = 1.f / s;
    for (int d = 0; d < 48; d++) sAt[tid * 48 + d] *= inv;
  }
  __syncthreads();
  for (int i = tid; i < 2304; i += 256) {
    int o = i / 48, d = i % 48;
    float a = 0.f;
#pragma unroll 8
    for (int c = 0; c < 48; c++) a = fmaf(po[o * 48 + c], sAt[c * 48 + d], a);
    M[(size_t)b * 2304 + i] = a;
  }
}

// ---------------------------------------------------------------------------
// Launch (dw_v forked onto side stream; round-16 structure)
// ---------------------------------------------------------------------------
extern "C" void kernel_launch(void* const* d_in, const int* in_sizes, int n_in,
                              void* d_out, int out_size) {
  (void)in_sizes; (void)n_in; (void)out_size;
  const float* x      = (const float*)d_in[0];
  const float* pe_w   = (const float*)d_in[1];
  const float* n1_w   = (const float*)d_in[2];
  const float* n1_b   = (const float*)d_in[3];
  const float* temp   = (const float*)d_in[4];
  const float* qkv_w  = (const float*)d_in[5];
  const float* qkv_dw = (const float*)d_in[6];
  const float* po_w   = (const float*)d_in[7];
  const float* n2_w   = (const float*)d_in[8];
  const float* n2_b   = (const float*)d_in[9];
  const float* pi_w   = (const float*)d_in[10];
  const float* ffn_dw = (const float*)d_in[11];
  const float* fo_w   = (const float*)d_in[12];
  float* out = (float*)d_out;

  float *part, *gfin, *M;
  __half *patch, *qkv0, *qkv, *first, *hbuf, *gate;
  cudaGetSymbolAddress((void**)&patch, g_patch);
  cudaGetSymbolAddress((void**)&qkv0,  g_qkv0);
  cudaGetSymbolAddress((void**)&qkv,   g_qkv);
  cudaGetSymbolAddress((void**)&first, g_first);
  cudaGetSymbolAddress((void**)&hbuf,  g_hbuf);
  cudaGetSymbolAddress((void**)&gate,  g_gate);
  cudaGetSymbolAddress((void**)&part,  g_part);
  cudaGetSymbolAddress((void**)&gfin,  g_gfin);
  cudaGetSymbolAddress((void**)&M,     g_M);

  constexpr int SM_T48 = (48 * 132 + 48 * 52 + 352) * 4;   // 36736
  constexpr int SM_PI  = (48 * 132 + 48 * 68 + 352) * 4;   // 39808
  constexpr int SM_FO  = (64 * 132 + 64 * 52 + 352) * 4;   // 48512

  static cudaStream_t s2 = nullptr;
  static cudaEvent_t evFork = nullptr, evJoin = nullptr;
  if (s2 == nullptr) {
    cudaStreamCreateWithFlags(&s2, cudaStreamNonBlocking);
    cudaEventCreateWithFlags(&evFork, cudaEventDisableTiming);
    cudaEventCreateWithFlags(&evJoin, cudaEventDisableTiming);
    cudaFuncSetAttribute(
        k_tgemm<127, 64, 48, 1, false, true, false, __half, __half, float>,
        cudaFuncAttributeMaxDynamicSharedMemorySize, SM_FO);
  }

  int gpix = Bb * Np / 128;  // 4096 pixel-tiles

  // 1. patch embed (fp16 out)
  k_pe<<<Bb * Hh, 128>>>(x, pe_w, patch);

  // 2. LN(patch) -> qkv 1x1 (48 -> 144), fp16 out; 3 CO-tiles per block
  k_tgemm<48, 48, 48, 3, true, false, false, __half, float, __half>
      <<<dim3(1, gpix), 192, SM_T48>>>(patch, Cc, 0, qkv_w, n1_w, n1_b,
                                       nullptr, 0, qkv0, C3, C3);

  // fork: dw on v-channels runs concurrently with dw_qk + gram chain
  cudaEventRecord(evFork, 0);
  cudaStreamWaitEvent(s2, evFork, 0);
  k_dw<<<(Bb * 48 * Hh * (Ww / 16) + 255) / 256, 256, 0, s2>>>(
      qkv0, qkv_dw, qkv, 96, 48);
  cudaEventRecord(evJoin, s2);

  // 3. depthwise 3x3 on q,k channels (stream 0)
  k_dw<<<(Bb * 96 * Hh * (Ww / 16) + 255) / 256, 256>>>(qkv0, qkv_dw, qkv, 0,
                                                        96);

  // 4-6. gram -> reduce -> softmax + fold po_w into M
  k_gram<<<Bb * NPART, 192>>>(qkv, part);
  k_red<<<(Bb * GSLOTS + 255) / 256, 256>>>(part, gfin);
  k_att<<<Bb, 256>>>(gfin, temp, po_w, M);

  // join: attn-v GEMM needs dw'd v
  cudaStreamWaitEvent((cudaStream_t)0, evJoin, 0);

  // 7. first = patch + M @ v   (fp16 residual + out)
  k_tgemm<48, 48, 48, 1, false, true, true, __half, __half, __half>
      <<<dim3(1, gpix), 192, SM_T48>>>(qkv, C3, 96, M, nullptr, nullptr, patch,
                                       Cc, first, Cc, Cc);

  // 8. LN(first) -> pi 1x1 (48 -> 254), fp16 out; 4 CO-tiles per block
  k_tgemm<48, 48, 64, 4, true, false, false, __half, float, __half>
      <<<dim3(1, gpix), 256, SM_PI>>>(first, Cc, 0, pi_w, n2_w, n2_b, nullptr,
                                      0, hbuf, HID2, HID2);

  // 9. depthwise 3x3 + exact-gelu gating (254 -> 127), fp16, 16 px/thread
  k_dwgelu<<<(Bb * HID * Hh * (Ww / 16) + 127) / 128, 128>>>(hbuf, ffn_dw,
                                                             gate);

  // 10. out = first + fo 1x1 (127 -> 48), fp32 out (fp16 residual)
  k_tgemm<127, 64, 48, 1, false, true, false, __half, __half, float>
      <<<dim3(1, gpix), 192, SM_FO>>>(gate, HID, 0, fo_w, nullptr, nullptr,
                                      first, Cc, out, Cc, Cc);
}